// round 15
// baseline (speedup 1.0000x reference)
#include <cuda_runtime.h>
#include <cuda_bf16.h>
#include <cstdint>

#define NN 100000
#define EE 1600000
#define HID_F 128
#define OUT_F 64
#define NB_SCAN 98    // ceil(NN/1024)
#define SPMM_GRID 592 // 4 blocks/SM on 148 SMs

// ---------------- scratch (static device globals; zero-initialized at load) ----------------
// INVARIANT: g_outdeg/g_indeg/g_w/g_vacc are ZERO on entry to kernel_launch and are
// restored to zero by the tail of the graph (k_tail_zero + k_final's self-zero).
__device__ __align__(128) int      g_outdeg[NN];
__device__ __align__(128) int      g_indeg[NN];
__device__ __align__(128) float    g_c_dst[NN];
__device__ __align__(128) int      g_rowptr[NN + 1];
__device__ __align__(128) int      g_cursor[NN];
__device__ __align__(128) int      g_csr_src[EE];
__device__ __align__(128) float    g_w[NN];                    // w[s] = sum_{e:src=s} c_dst[dst_e]
__device__ __align__(128) uint32_t g_hb[(size_t)NN * 64];      // layer1 out (c_src-scaled), bf16x2
__device__ __align__(128) float    g_vacc[HID_F];              // sum_s w[s]*relu(...)[s]
__device__ __align__(128) int      g_bsum[NB_SCAN];

// ---------------- host-side fork/join objects (created at load, before checkpoints) ----
struct HostCtx {
    cudaStream_t s2;
    cudaEvent_t ev_fork, ev_join, ev_spmm, ev_tail;
    HostCtx() {
        cudaStreamCreateWithFlags(&s2, cudaStreamNonBlocking);
        cudaEventCreateWithFlags(&ev_fork, cudaEventDisableTiming);
        cudaEventCreateWithFlags(&ev_join, cudaEventDisableTiming);
        cudaEventCreateWithFlags(&ev_spmm, cudaEventDisableTiming);
        cudaEventCreateWithFlags(&ev_tail, cudaEventDisableTiming);
    }
};
static HostCtx g_ctx;

// ---------------- helpers ----------------
__device__ __forceinline__ uint32_t smem_u32(const void* p) {
    uint32_t a;
    asm("{ .reg .u64 t; cvta.to.shared.u64 t, %1; cvt.u32.u64 %0, t; }" : "=r"(a) : "l"(p));
    return a;
}

#define LDSM_X4_T(r0, r1, r2, r3, addr) \
    asm volatile("ldmatrix.sync.aligned.m8n8.x4.trans.shared.b16 {%0,%1,%2,%3}, [%4];" \
                 : "=r"(r0), "=r"(r1), "=r"(r2), "=r"(r3) : "r"(addr))

#define MMA_BF16(d, a0, a1, a2, a3, b0, b1) \
    asm volatile("mma.sync.aligned.m16n8k16.row.col.f32.bf16.bf16.f32 " \
                 "{%0,%1,%2,%3}, {%4,%5,%6,%7}, {%8,%9}, {%0,%1,%2,%3};" \
                 : "+f"((d)[0]), "+f"((d)[1]), "+f"((d)[2]), "+f"((d)[3]) \
                 : "r"(a0), "r"(a1), "r"(a2), "r"(a3), "r"(b0), "r"(b1))

__device__ __forceinline__ uint32_t pack_bf2(float f0, float f1) {
    __nv_bfloat162 t = __floats2bfloat162_rn(f0, f1);
    return *reinterpret_cast<uint32_t*>(&t);
}

// ---------------- kernels ----------------

// BOTH degrees in one edge-list pass: 8 independent atomics in flight per thread
// (latency-bound path per ncu: L2 46%, issue 5.5% -> double MLP, ~same duration).
__global__ void k_degree(const int* __restrict__ src, const int* __restrict__ dst) {
    int i = blockIdx.x * blockDim.x + threadIdx.x;
    int stride = gridDim.x * blockDim.x;
    const int4* s4 = (const int4*)src;
    const int4* d4 = (const int4*)dst;
    for (int e = i; e < EE / 4; e += stride) {
        int4 sv = s4[e];
        int4 dv = d4[e];
        atomicAdd(&g_outdeg[sv.x], 1);
        atomicAdd(&g_outdeg[sv.y], 1);
        atomicAdd(&g_outdeg[sv.z], 1);
        atomicAdd(&g_outdeg[sv.w], 1);
        atomicAdd(&g_indeg[dv.x], 1);
        atomicAdd(&g_indeg[dv.y], 1);
        atomicAdd(&g_indeg[dv.z], 1);
        atomicAdd(&g_indeg[dv.w], 1);
    }
}

// Per-block exclusive scan of g_indeg (local) + block totals; fused c_dst computation.
__global__ void __launch_bounds__(1024) k_scan1() {
    __shared__ int wsum[32];
    int tid = threadIdx.x;
    int lane = tid & 31, wid = tid >> 5;
    int i = blockIdx.x * 1024 + tid;
    int v = (i < NN) ? g_indeg[i] : 0;

    if (i < NN) g_c_dst[i] = rsqrtf((float)max(v, 1));

    int x = v;
#pragma unroll
    for (int off = 1; off < 32; off <<= 1) {
        int y = __shfl_up_sync(0xffffffffu, x, off);
        if (lane >= off) x += y;
    }
    if (lane == 31) wsum[wid] = x;
    __syncthreads();
    if (wid == 0) {
        int s = wsum[lane];
#pragma unroll
        for (int off = 1; off < 32; off <<= 1) {
            int y = __shfl_up_sync(0xffffffffu, s, off);
            if (lane >= off) s += y;
        }
        wsum[lane] = s;
    }
    __syncthreads();
    int excl = x - v + ((wid == 0) ? 0 : wsum[wid - 1]);
    if (i < NN) g_rowptr[i] = excl;
    if (tid == 0) g_bsum[blockIdx.x] = wsum[31];
}

// Add block offsets; init cursor; rowptr[NN] = EE.
__global__ void __launch_bounds__(1024) k_scan3() {
    __shared__ int s_off;
    int tid = threadIdx.x;
    int b = blockIdx.x;
    if (tid < 32) {
        int off = 0;
#pragma unroll
        for (int c = 0; c < (NB_SCAN + 31) / 32; c++) {
            int idx = c * 32 + tid;
            if (idx < b) off += g_bsum[idx];
        }
#pragma unroll
        for (int o = 16; o > 0; o >>= 1) off += __shfl_down_sync(0xffffffffu, off, o);
        if (tid == 0) s_off = off;
    }
    __syncthreads();
    int i = b * 1024 + tid;
    if (i < NN) {
        int rp = g_rowptr[i] + s_off;
        g_rowptr[i] = rp;
        g_cursor[i] = rp;
    }
    if (i == 0) g_rowptr[NN] = EE;
}

// CSR scatter (by dst) fused with w[s] accumulation; int4 edge reads.
__global__ void k_scatter_wsum(const int* __restrict__ src, const int* __restrict__ dst) {
    int i = blockIdx.x * blockDim.x + threadIdx.x;
    int stride = gridDim.x * blockDim.x;
    const int4* s4 = (const int4*)src;
    const int4* d4 = (const int4*)dst;
    for (int e = i; e < EE / 4; e += stride) {
        int4 sv = s4[e];
        int4 dv = d4[e];
        int p0 = atomicAdd(&g_cursor[dv.x], 1);
        int p1 = atomicAdd(&g_cursor[dv.y], 1);
        int p2 = atomicAdd(&g_cursor[dv.z], 1);
        int p3 = atomicAdd(&g_cursor[dv.w], 1);
        g_csr_src[p0] = sv.x;
        g_csr_src[p1] = sv.y;
        g_csr_src[p2] = sv.z;
        g_csr_src[p3] = sv.w;
        atomicAdd(&g_w[sv.x], g_c_dst[dv.x]);
        atomicAdd(&g_w[sv.y], g_c_dst[dv.y]);
        atomicAdd(&g_w[sv.z], g_c_dst[dv.z]);
        atomicAdd(&g_w[sv.w], g_c_dst[dv.w]);
    }
}

// -------- 2-term bf16 mma.sync GEMM: g_hb = bf16((feat*c_src) @ W1) --------
// W split hi/lo (W truncation is a correlated bias -> must be corrected);
// A single bf16 (per-node random error, averages out; ~4e-5 residual).
#define TPAD 136
#define SM_WH 0
#define SM_WL (SM_WH + 128 * TPAD * 2)
#define SM_GEMM_TOTAL (SM_WL + 128 * TPAD * 2)  // 69632

__global__ void __launch_bounds__(256, 2)
k_gemm_mma(const float* __restrict__ feat, const float* __restrict__ W) {
    extern __shared__ char sm[];
    uint32_t smb = smem_u32(sm);
    int tid = threadIdx.x, lane = tid & 31, wid = tid >> 5;
    int row0 = blockIdx.x * 128;

    // stage W: natural [k][n] layout, hi/lo split
    for (int idx = tid; idx < 128 * 128; idx += 256) {
        int k = idx >> 7, n = idx & 127;
        float f = W[idx];
        __nv_bfloat16 bh = __float2bfloat16(f);
        float fl = f - __bfloat162float(bh);
        uint32_t boff = (uint32_t)(k * TPAD + n) * 2u;
        *(__nv_bfloat16*)(sm + SM_WH + boff) = bh;
        *(__nv_bfloat16*)(sm + SM_WL + boff) = __float2bfloat16(fl);
    }
    __syncthreads();

    int g = lane >> 2, t = lane & 3;
    int rowA = row0 + wid * 16 + g;
    int rowB = rowA + 8;
    bool vA = rowA < NN, vB = rowB < NN;
    float sA = vA ? rsqrtf((float)max(g_outdeg[rowA], 1)) : 0.0f;
    float sB = vB ? rsqrtf((float)max(g_outdeg[rowB], 1)) : 0.0f;
    const float2* pA = (const float2*)(feat + (size_t)(vA ? rowA : 0) * 128);
    const float2* pB = (const float2*)(feat + (size_t)(vB ? rowB : 0) * 128);

    float acc[16][4];
#pragma unroll
    for (int i = 0; i < 16; i++)
#pragma unroll
        for (int j = 0; j < 4; j++) acc[i][j] = 0.0f;

    int lrow = lane & 15;
    int lsel = (lane >> 4) << 3;
    uint32_t w_base = smb + SM_WH + (uint32_t)(lrow * TPAD + lsel) * 2u;
    const uint32_t WL_OFF = SM_WL - SM_WH;

#pragma unroll 1
    for (int ks = 0; ks < 8; ks++) {
        int c0 = ks * 8 + t;
        int c1 = c0 + 4;
        float2 f0 = pA[c0], f1 = pB[c0], f2 = pA[c1], f3 = pB[c1];
        uint32_t ah0 = pack_bf2(f0.x * sA, f0.y * sA);
        uint32_t ah1 = pack_bf2(f1.x * sB, f1.y * sB);
        uint32_t ah2 = pack_bf2(f2.x * sA, f2.y * sA);
        uint32_t ah3 = pack_bf2(f3.x * sB, f3.y * sB);

        uint32_t wrow = w_base + (uint32_t)ks * (16u * TPAD * 2u);
#pragma unroll
        for (int np = 0; np < 8; np++) {
            uint32_t waddr = wrow + (uint32_t)np * 32u;
            uint32_t bh0, bh1, bh2, bh3, bl0, bl1, bl2, bl3;
            LDSM_X4_T(bh0, bh1, bh2, bh3, waddr);
            LDSM_X4_T(bl0, bl1, bl2, bl3, waddr + WL_OFF);
            MMA_BF16(acc[2 * np],     ah0, ah1, ah2, ah3, bh0, bh1);
            MMA_BF16(acc[2 * np + 1], ah0, ah1, ah2, ah3, bh2, bh3);
            MMA_BF16(acc[2 * np],     ah0, ah1, ah2, ah3, bl0, bl1);
            MMA_BF16(acc[2 * np + 1], ah0, ah1, ah2, ah3, bl2, bl3);
        }
    }

#pragma unroll
    for (int nt = 0; nt < 16; nt++) {
        uint32_t plo = pack_bf2(acc[nt][0], acc[nt][1]);
        uint32_t phi = pack_bf2(acc[nt][2], acc[nt][3]);
        int ci = nt * 4 + t;
        if (vA) g_hb[(size_t)rowA * 64 + ci] = plo;
        if (vB) g_hb[(size_t)rowB * 64 + ci] = phi;
    }
}

// Persistent CSR aggregation: warp-per-node, register-resident vacc,
// one block reduce + 128 atomics per block.
__global__ void __launch_bounds__(256) k_spmm_vacc(const float* __restrict__ b1) {
    __shared__ float sv[8][HID_F];
    int tid = threadIdx.x;
    int lane = tid & 31, wid = tid >> 5;

    float4 bb = *(const float4*)(b1 + lane * 4);
    float4 vloc = make_float4(0.f, 0.f, 0.f, 0.f);

    for (int gw = blockIdx.x * 8 + wid; gw < NN; gw += SPMM_GRID * 8) {
        int beg = g_rowptr[gw], end = g_rowptr[gw + 1];
        float4 a0 = make_float4(0.f, 0.f, 0.f, 0.f);
        float4 a1 = make_float4(0.f, 0.f, 0.f, 0.f);
        int j = beg;
        for (; j + 3 < end; j += 4) {
            int s0 = g_csr_src[j], s1 = g_csr_src[j + 1];
            int s2 = g_csr_src[j + 2], s3 = g_csr_src[j + 3];
            uint2 v0 = *(const uint2*)(g_hb + (size_t)s0 * 64 + lane * 2);
            uint2 v1 = *(const uint2*)(g_hb + (size_t)s1 * 64 + lane * 2);
            uint2 v2 = *(const uint2*)(g_hb + (size_t)s2 * 64 + lane * 2);
            uint2 v3 = *(const uint2*)(g_hb + (size_t)s3 * 64 + lane * 2);
            float2 f00 = __bfloat1622float2(*reinterpret_cast<__nv_bfloat162*>(&v0.x));
            float2 f01 = __bfloat1622float2(*reinterpret_cast<__nv_bfloat162*>(&v0.y));
            float2 f10 = __bfloat1622float2(*reinterpret_cast<__nv_bfloat162*>(&v1.x));
            float2 f11 = __bfloat1622float2(*reinterpret_cast<__nv_bfloat162*>(&v1.y));
            float2 f20 = __bfloat1622float2(*reinterpret_cast<__nv_bfloat162*>(&v2.x));
            float2 f21 = __bfloat1622float2(*reinterpret_cast<__nv_bfloat162*>(&v2.y));
            float2 f30 = __bfloat1622float2(*reinterpret_cast<__nv_bfloat162*>(&v3.x));
            float2 f31 = __bfloat1622float2(*reinterpret_cast<__nv_bfloat162*>(&v3.y));
            a0.x += f00.x + f20.x; a0.y += f00.y + f20.y;
            a0.z += f01.x + f21.x; a0.w += f01.y + f21.y;
            a1.x += f10.x + f30.x; a1.y += f10.y + f30.y;
            a1.z += f11.x + f31.x; a1.w += f11.y + f31.y;
        }
        for (; j < end; j++) {
            int s = g_csr_src[j];
            uint2 v = *(const uint2*)(g_hb + (size_t)s * 64 + lane * 2);
            float2 f0 = __bfloat1622float2(*reinterpret_cast<__nv_bfloat162*>(&v.x));
            float2 f1 = __bfloat1622float2(*reinterpret_cast<__nv_bfloat162*>(&v.y));
            a0.x += f0.x; a0.y += f0.y; a0.z += f1.x; a0.w += f1.y;
        }
        float cd = g_c_dst[gw];
        float cs = rsqrtf((float)max(g_outdeg[gw], 1));
        float wn = g_w[gw] * cs;
        vloc.x = fmaf(fmaxf(fmaf(a0.x + a1.x, cd, bb.x), 0.0f), wn, vloc.x);
        vloc.y = fmaf(fmaxf(fmaf(a0.y + a1.y, cd, bb.y), 0.0f), wn, vloc.y);
        vloc.z = fmaf(fmaxf(fmaf(a0.z + a1.z, cd, bb.z), 0.0f), wn, vloc.z);
        vloc.w = fmaf(fmaxf(fmaf(a0.w + a1.w, cd, bb.w), 0.0f), wn, vloc.w);
    }

    *(float4*)&sv[wid][lane * 4] = vloc;
    __syncthreads();
    if (tid < HID_F) {
        float s = 0.0f;
#pragma unroll
        for (int w = 0; w < 8; w++) s += sv[w][tid];
        atomicAdd(&g_vacc[tid], s);
    }
}

// out = (g_vacc @ W2) / N + b2 -> [1, 64]; self-restores g_vacc to zero.
__global__ void k_final(const float* __restrict__ W2, const float* __restrict__ b2,
                        float* __restrict__ out) {
    __shared__ float v[HID_F];
    int tid = threadIdx.x;
    if (tid < HID_F) v[tid] = g_vacc[tid];
    __syncthreads();
    if (tid < HID_F) g_vacc[tid] = 0.0f;   // restore zero-invariant for next replay
    if (tid < OUT_F) {
        float s = 0.0f;
#pragma unroll 8
        for (int k = 0; k < HID_F; k++) s = fmaf(v[k], W2[k * OUT_F + tid], s);
        out[tid] = s * (1.0f / (float)NN) + b2[tid];
    }
}

// Restore zero-invariant for outdeg/indeg/w (runs on s2, overlapped with k_final).
__global__ void k_tail_zero() {
    int i = blockIdx.x * blockDim.x + threadIdx.x;
    int stride = gridDim.x * blockDim.x;
    for (int t = i; t < NN; t += stride) {
        g_outdeg[t] = 0; g_indeg[t] = 0; g_w[t] = 0.0f;
    }
}

// ---------------- launch ----------------
extern "C" void kernel_launch(void* const* d_in, const int* in_sizes, int n_in,
                              void* d_out, int out_size) {
    const float* feat = (const float*)d_in[0];
    const int*   src  = (const int*)d_in[1];
    const int*   dst  = (const int*)d_in[2];
    const float* W1   = (const float*)d_in[3];
    const float* b1   = (const float*)d_in[4];
    const float* W2   = (const float*)d_in[5];
    const float* b2   = (const float*)d_in[6];
    float* out = (float*)d_out;

    (void)in_sizes; (void)n_in; (void)out_size;

    cudaFuncSetAttribute(k_gemm_mma, cudaFuncAttributeMaxDynamicSharedMemorySize, SM_GEMM_TOTAL);

    // Single combined degree pass (both atomics, 8 in flight per thread).
    k_degree<<<1024, 256>>>(src, dst);

    // Fork: GEMM (s2, needs outdeg) alongside scan/scatter (default, needs indeg).
    cudaEventRecord(g_ctx.ev_fork, 0);
    cudaStreamWaitEvent(g_ctx.s2, g_ctx.ev_fork, 0);
    k_gemm_mma<<<(NN + 127) / 128, 256, SM_GEMM_TOTAL, g_ctx.s2>>>(feat, W1);
    cudaEventRecord(g_ctx.ev_join, g_ctx.s2);

    k_scan1<<<NB_SCAN, 1024>>>();
    k_scan3<<<NB_SCAN, 1024>>>();
    k_scatter_wsum<<<1024, 256>>>(src, dst);

    // Join before SpMM (needs g_hb from s2, CSR/w/c_dst from default).
    cudaStreamWaitEvent(0, g_ctx.ev_join, 0);
    k_spmm_vacc<<<SPMM_GRID, 256>>>(b1);

    // Tail: restore zero-invariant on s2, overlapped with k_final on default.
    cudaEventRecord(g_ctx.ev_spmm, 0);
    cudaStreamWaitEvent(g_ctx.s2, g_ctx.ev_spmm, 0);
    k_tail_zero<<<256, 256, 0, g_ctx.s2>>>();
    cudaEventRecord(g_ctx.ev_tail, g_ctx.s2);

    k_final<<<1, 128>>>(W2, b2, out);
    cudaStreamWaitEvent(0, g_ctx.ev_tail, 0);
}

// round 16
// speedup vs baseline: 1.0452x; 1.0452x over previous
#include <cuda_runtime.h>
#include <cuda_bf16.h>
#include <cstdint>

#define NN 100000
#define EE 1600000
#define HID_F 128
#define OUT_F 64
#define NB_SCAN 98    // ceil(NN/1024)
#define SPMM_GRID 592 // 4 blocks/SM on 148 SMs

// ---------------- scratch (static device globals; zero-initialized at load) ----------------
// INVARIANT: g_outdeg/g_indeg/g_w/g_vacc are ZERO on entry to kernel_launch and are
// restored to zero by the tail of the graph (k_tail_zero + k_final's self-zero).
__device__ __align__(128) int      g_outdeg[NN];
__device__ __align__(128) int      g_indeg[NN];
__device__ __align__(128) float    g_c_dst[NN];
__device__ __align__(128) int      g_rowptr[NN + 1];
__device__ __align__(128) int      g_cursor[NN];
__device__ __align__(128) int      g_csr_src[EE];
__device__ __align__(128) float    g_w[NN];                    // w[s] = sum_{e:src=s} c_dst[dst_e]
__device__ __align__(128) uint32_t g_hb[(size_t)NN * 64];      // layer1 out (c_src-scaled), bf16x2
__device__ __align__(128) float    g_vacc[HID_F];              // sum_s w[s]*relu(...)[s]
__device__ __align__(128) int      g_bsum[NB_SCAN];

// ---------------- host-side fork/join objects (created at load, before checkpoints) ----
struct HostCtx {
    cudaStream_t s2;
    cudaEvent_t ev_fork, ev_join, ev_spmm, ev_tail;
    HostCtx() {
        cudaStreamCreateWithFlags(&s2, cudaStreamNonBlocking);
        cudaEventCreateWithFlags(&ev_fork, cudaEventDisableTiming);
        cudaEventCreateWithFlags(&ev_join, cudaEventDisableTiming);
        cudaEventCreateWithFlags(&ev_spmm, cudaEventDisableTiming);
        cudaEventCreateWithFlags(&ev_tail, cudaEventDisableTiming);
    }
};
static HostCtx g_ctx;

// ---------------- helpers ----------------
__device__ __forceinline__ uint32_t smem_u32(const void* p) {
    uint32_t a;
    asm("{ .reg .u64 t; cvta.to.shared.u64 t, %1; cvt.u32.u64 %0, t; }" : "=r"(a) : "l"(p));
    return a;
}

#define LDSM_X4_T(r0, r1, r2, r3, addr) \
    asm volatile("ldmatrix.sync.aligned.m8n8.x4.trans.shared.b16 {%0,%1,%2,%3}, [%4];" \
                 : "=r"(r0), "=r"(r1), "=r"(r2), "=r"(r3) : "r"(addr))

#define MMA_BF16(d, a0, a1, a2, a3, b0, b1) \
    asm volatile("mma.sync.aligned.m16n8k16.row.col.f32.bf16.bf16.f32 " \
                 "{%0,%1,%2,%3}, {%4,%5,%6,%7}, {%8,%9}, {%0,%1,%2,%3};" \
                 : "+f"((d)[0]), "+f"((d)[1]), "+f"((d)[2]), "+f"((d)[3]) \
                 : "r"(a0), "r"(a1), "r"(a2), "r"(a3), "r"(b0), "r"(b1))

__device__ __forceinline__ uint32_t pack_bf2(float f0, float f1) {
    __nv_bfloat162 t = __floats2bfloat162_rn(f0, f1);
    return *reinterpret_cast<uint32_t*>(&t);
}

__device__ __forceinline__ float2 bf2f(uint32_t u) {
    return __bfloat1622float2(*reinterpret_cast<__nv_bfloat162*>(&u));
}

// ---------------- kernels ----------------

// out-degree only (stream 2, feeds GEMM); int4 edge reads for MLP
__global__ void k_deg_out(const int* __restrict__ src) {
    int i = blockIdx.x * blockDim.x + threadIdx.x;
    int stride = gridDim.x * blockDim.x;
    const int4* s4 = (const int4*)src;
    for (int e = i; e < EE / 4; e += stride) {
        int4 v = s4[e];
        atomicAdd(&g_outdeg[v.x], 1);
        atomicAdd(&g_outdeg[v.y], 1);
        atomicAdd(&g_outdeg[v.z], 1);
        atomicAdd(&g_outdeg[v.w], 1);
    }
}

// in-degree only (default stream, feeds scan/CSR); int4 edge reads
__global__ void k_deg_in(const int* __restrict__ dst) {
    int i = blockIdx.x * blockDim.x + threadIdx.x;
    int stride = gridDim.x * blockDim.x;
    const int4* d4 = (const int4*)dst;
    for (int e = i; e < EE / 4; e += stride) {
        int4 v = d4[e];
        atomicAdd(&g_indeg[v.x], 1);
        atomicAdd(&g_indeg[v.y], 1);
        atomicAdd(&g_indeg[v.z], 1);
        atomicAdd(&g_indeg[v.w], 1);
    }
}

// Per-block exclusive scan of g_indeg (local) + block totals; fused c_dst computation.
__global__ void __launch_bounds__(1024) k_scan1() {
    __shared__ int wsum[32];
    int tid = threadIdx.x;
    int lane = tid & 31, wid = tid >> 5;
    int i = blockIdx.x * 1024 + tid;
    int v = (i < NN) ? g_indeg[i] : 0;

    if (i < NN) g_c_dst[i] = rsqrtf((float)max(v, 1));

    int x = v;
#pragma unroll
    for (int off = 1; off < 32; off <<= 1) {
        int y = __shfl_up_sync(0xffffffffu, x, off);
        if (lane >= off) x += y;
    }
    if (lane == 31) wsum[wid] = x;
    __syncthreads();
    if (wid == 0) {
        int s = wsum[lane];
#pragma unroll
        for (int off = 1; off < 32; off <<= 1) {
            int y = __shfl_up_sync(0xffffffffu, s, off);
            if (lane >= off) s += y;
        }
        wsum[lane] = s;
    }
    __syncthreads();
    int excl = x - v + ((wid == 0) ? 0 : wsum[wid - 1]);
    if (i < NN) g_rowptr[i] = excl;
    if (tid == 0) g_bsum[blockIdx.x] = wsum[31];
}

// Add block offsets; init cursor; rowptr[NN] = EE.
__global__ void __launch_bounds__(1024) k_scan3() {
    __shared__ int s_off;
    int tid = threadIdx.x;
    int b = blockIdx.x;
    if (tid < 32) {
        int off = 0;
#pragma unroll
        for (int c = 0; c < (NB_SCAN + 31) / 32; c++) {
            int idx = c * 32 + tid;
            if (idx < b) off += g_bsum[idx];
        }
#pragma unroll
        for (int o = 16; o > 0; o >>= 1) off += __shfl_down_sync(0xffffffffu, off, o);
        if (tid == 0) s_off = off;
    }
    __syncthreads();
    int i = b * 1024 + tid;
    if (i < NN) {
        int rp = g_rowptr[i] + s_off;
        g_rowptr[i] = rp;
        g_cursor[i] = rp;
    }
    if (i == 0) g_rowptr[NN] = EE;
}

// CSR scatter (by dst) fused with w[s] accumulation; int4 edge reads.
__global__ void k_scatter_wsum(const int* __restrict__ src, const int* __restrict__ dst) {
    int i = blockIdx.x * blockDim.x + threadIdx.x;
    int stride = gridDim.x * blockDim.x;
    const int4* s4 = (const int4*)src;
    const int4* d4 = (const int4*)dst;
    for (int e = i; e < EE / 4; e += stride) {
        int4 sv = s4[e];
        int4 dv = d4[e];
        int p0 = atomicAdd(&g_cursor[dv.x], 1);
        int p1 = atomicAdd(&g_cursor[dv.y], 1);
        int p2 = atomicAdd(&g_cursor[dv.z], 1);
        int p3 = atomicAdd(&g_cursor[dv.w], 1);
        g_csr_src[p0] = sv.x;
        g_csr_src[p1] = sv.y;
        g_csr_src[p2] = sv.z;
        g_csr_src[p3] = sv.w;
        atomicAdd(&g_w[sv.x], g_c_dst[dv.x]);
        atomicAdd(&g_w[sv.y], g_c_dst[dv.y]);
        atomicAdd(&g_w[sv.z], g_c_dst[dv.z]);
        atomicAdd(&g_w[sv.w], g_c_dst[dv.w]);
    }
}

// -------- 2-term bf16 mma.sync GEMM: g_hb = bf16((feat*c_src) @ W1) --------
// W split hi/lo (W truncation is a correlated bias -> must be corrected);
// A single bf16 (per-node random error, averages out; ~4e-5 residual).
#define TPAD 136
#define SM_WH 0
#define SM_WL (SM_WH + 128 * TPAD * 2)
#define SM_GEMM_TOTAL (SM_WL + 128 * TPAD * 2)  // 69632

__global__ void __launch_bounds__(256, 2)
k_gemm_mma(const float* __restrict__ feat, const float* __restrict__ W) {
    extern __shared__ char sm[];
    uint32_t smb = smem_u32(sm);
    int tid = threadIdx.x, lane = tid & 31, wid = tid >> 5;
    int row0 = blockIdx.x * 128;

    // stage W: natural [k][n] layout, hi/lo split
    for (int idx = tid; idx < 128 * 128; idx += 256) {
        int k = idx >> 7, n = idx & 127;
        float f = W[idx];
        __nv_bfloat16 bh = __float2bfloat16(f);
        float fl = f - __bfloat162float(bh);
        uint32_t boff = (uint32_t)(k * TPAD + n) * 2u;
        *(__nv_bfloat16*)(sm + SM_WH + boff) = bh;
        *(__nv_bfloat16*)(sm + SM_WL + boff) = __float2bfloat16(fl);
    }
    __syncthreads();

    int g = lane >> 2, t = lane & 3;
    int rowA = row0 + wid * 16 + g;
    int rowB = rowA + 8;
    bool vA = rowA < NN, vB = rowB < NN;
    float sA = vA ? rsqrtf((float)max(g_outdeg[rowA], 1)) : 0.0f;
    float sB = vB ? rsqrtf((float)max(g_outdeg[rowB], 1)) : 0.0f;
    const float2* pA = (const float2*)(feat + (size_t)(vA ? rowA : 0) * 128);
    const float2* pB = (const float2*)(feat + (size_t)(vB ? rowB : 0) * 128);

    float acc[16][4];
#pragma unroll
    for (int i = 0; i < 16; i++)
#pragma unroll
        for (int j = 0; j < 4; j++) acc[i][j] = 0.0f;

    int lrow = lane & 15;
    int lsel = (lane >> 4) << 3;
    uint32_t w_base = smb + SM_WH + (uint32_t)(lrow * TPAD + lsel) * 2u;
    const uint32_t WL_OFF = SM_WL - SM_WH;

#pragma unroll 1
    for (int ks = 0; ks < 8; ks++) {
        int c0 = ks * 8 + t;
        int c1 = c0 + 4;
        float2 f0 = pA[c0], f1 = pB[c0], f2 = pA[c1], f3 = pB[c1];
        uint32_t ah0 = pack_bf2(f0.x * sA, f0.y * sA);
        uint32_t ah1 = pack_bf2(f1.x * sB, f1.y * sB);
        uint32_t ah2 = pack_bf2(f2.x * sA, f2.y * sA);
        uint32_t ah3 = pack_bf2(f3.x * sB, f3.y * sB);

        uint32_t wrow = w_base + (uint32_t)ks * (16u * TPAD * 2u);
#pragma unroll
        for (int np = 0; np < 8; np++) {
            uint32_t waddr = wrow + (uint32_t)np * 32u;
            uint32_t bh0, bh1, bh2, bh3, bl0, bl1, bl2, bl3;
            LDSM_X4_T(bh0, bh1, bh2, bh3, waddr);
            LDSM_X4_T(bl0, bl1, bl2, bl3, waddr + WL_OFF);
            MMA_BF16(acc[2 * np],     ah0, ah1, ah2, ah3, bh0, bh1);
            MMA_BF16(acc[2 * np + 1], ah0, ah1, ah2, ah3, bh2, bh3);
            MMA_BF16(acc[2 * np],     ah0, ah1, ah2, ah3, bl0, bl1);
            MMA_BF16(acc[2 * np + 1], ah0, ah1, ah2, ah3, bl2, bl3);
        }
    }

#pragma unroll
    for (int nt = 0; nt < 16; nt++) {
        uint32_t plo = pack_bf2(acc[nt][0], acc[nt][1]);
        uint32_t phi = pack_bf2(acc[nt][2], acc[nt][3]);
        int ci = nt * 4 + t;
        if (vA) g_hb[(size_t)rowA * 64 + ci] = plo;
        if (vB) g_hb[(size_t)rowB * 64 + ci] = phi;
    }
}

// Persistent CSR aggregation: warp-per-node, register-resident vacc.
// 8-deep gather pipeline (8 independent 256B row loads in flight per warp).
__global__ void __launch_bounds__(256) k_spmm_vacc(const float* __restrict__ b1) {
    __shared__ float sv[8][HID_F];
    int tid = threadIdx.x;
    int lane = tid & 31, wid = tid >> 5;

    float4 bb = *(const float4*)(b1 + lane * 4);
    float4 vloc = make_float4(0.f, 0.f, 0.f, 0.f);

    for (int gw = blockIdx.x * 8 + wid; gw < NN; gw += SPMM_GRID * 8) {
        int beg = g_rowptr[gw], end = g_rowptr[gw + 1];
        float4 a0 = make_float4(0.f, 0.f, 0.f, 0.f);
        float4 a1 = make_float4(0.f, 0.f, 0.f, 0.f);
        int j = beg;
        // 8-deep: 8 independent row gathers in flight
        for (; j + 7 < end; j += 8) {
            int s0 = g_csr_src[j],     s1 = g_csr_src[j + 1];
            int s2 = g_csr_src[j + 2], s3 = g_csr_src[j + 3];
            int s4 = g_csr_src[j + 4], s5 = g_csr_src[j + 5];
            int s6 = g_csr_src[j + 6], s7 = g_csr_src[j + 7];
            uint2 v0 = *(const uint2*)(g_hb + (size_t)s0 * 64 + lane * 2);
            uint2 v1 = *(const uint2*)(g_hb + (size_t)s1 * 64 + lane * 2);
            uint2 v2 = *(const uint2*)(g_hb + (size_t)s2 * 64 + lane * 2);
            uint2 v3 = *(const uint2*)(g_hb + (size_t)s3 * 64 + lane * 2);
            uint2 v4 = *(const uint2*)(g_hb + (size_t)s4 * 64 + lane * 2);
            uint2 v5 = *(const uint2*)(g_hb + (size_t)s5 * 64 + lane * 2);
            uint2 v6 = *(const uint2*)(g_hb + (size_t)s6 * 64 + lane * 2);
            uint2 v7 = *(const uint2*)(g_hb + (size_t)s7 * 64 + lane * 2);
            float2 f0x = bf2f(v0.x), f0y = bf2f(v0.y);
            float2 f1x = bf2f(v1.x), f1y = bf2f(v1.y);
            float2 f2x = bf2f(v2.x), f2y = bf2f(v2.y);
            float2 f3x = bf2f(v3.x), f3y = bf2f(v3.y);
            float2 f4x = bf2f(v4.x), f4y = bf2f(v4.y);
            float2 f5x = bf2f(v5.x), f5y = bf2f(v5.y);
            float2 f6x = bf2f(v6.x), f6y = bf2f(v6.y);
            float2 f7x = bf2f(v7.x), f7y = bf2f(v7.y);
            a0.x += (f0x.x + f2x.x) + (f4x.x + f6x.x);
            a0.y += (f0x.y + f2x.y) + (f4x.y + f6x.y);
            a0.z += (f0y.x + f2y.x) + (f4y.x + f6y.x);
            a0.w += (f0y.y + f2y.y) + (f4y.y + f6y.y);
            a1.x += (f1x.x + f3x.x) + (f5x.x + f7x.x);
            a1.y += (f1x.y + f3x.y) + (f5x.y + f7x.y);
            a1.z += (f1y.x + f3y.x) + (f5y.x + f7y.x);
            a1.w += (f1y.y + f3y.y) + (f5y.y + f7y.y);
        }
        for (; j + 3 < end; j += 4) {
            int s0 = g_csr_src[j],     s1 = g_csr_src[j + 1];
            int s2 = g_csr_src[j + 2], s3 = g_csr_src[j + 3];
            uint2 v0 = *(const uint2*)(g_hb + (size_t)s0 * 64 + lane * 2);
            uint2 v1 = *(const uint2*)(g_hb + (size_t)s1 * 64 + lane * 2);
            uint2 v2 = *(const uint2*)(g_hb + (size_t)s2 * 64 + lane * 2);
            uint2 v3 = *(const uint2*)(g_hb + (size_t)s3 * 64 + lane * 2);
            float2 f0x = bf2f(v0.x), f0y = bf2f(v0.y);
            float2 f1x = bf2f(v1.x), f1y = bf2f(v1.y);
            float2 f2x = bf2f(v2.x), f2y = bf2f(v2.y);
            float2 f3x = bf2f(v3.x), f3y = bf2f(v3.y);
            a0.x += f0x.x + f2x.x; a0.y += f0x.y + f2x.y;
            a0.z += f0y.x + f2y.x; a0.w += f0y.y + f2y.y;
            a1.x += f1x.x + f3x.x; a1.y += f1x.y + f3x.y;
            a1.z += f1y.x + f3y.x; a1.w += f1y.y + f3y.y;
        }
        for (; j < end; j++) {
            int s = g_csr_src[j];
            uint2 v = *(const uint2*)(g_hb + (size_t)s * 64 + lane * 2);
            float2 f0 = bf2f(v.x), f1 = bf2f(v.y);
            a0.x += f0.x; a0.y += f0.y; a0.z += f1.x; a0.w += f1.y;
        }
        float cd = g_c_dst[gw];
        float cs = rsqrtf((float)max(g_outdeg[gw], 1));
        float wn = g_w[gw] * cs;
        vloc.x = fmaf(fmaxf(fmaf(a0.x + a1.x, cd, bb.x), 0.0f), wn, vloc.x);
        vloc.y = fmaf(fmaxf(fmaf(a0.y + a1.y, cd, bb.y), 0.0f), wn, vloc.y);
        vloc.z = fmaf(fmaxf(fmaf(a0.z + a1.z, cd, bb.z), 0.0f), wn, vloc.z);
        vloc.w = fmaf(fmaxf(fmaf(a0.w + a1.w, cd, bb.w), 0.0f), wn, vloc.w);
    }

    *(float4*)&sv[wid][lane * 4] = vloc;
    __syncthreads();
    if (tid < HID_F) {
        float s = 0.0f;
#pragma unroll
        for (int w = 0; w < 8; w++) s += sv[w][tid];
        atomicAdd(&g_vacc[tid], s);
    }
}

// out = (g_vacc @ W2) / N + b2 -> [1, 64]; self-restores g_vacc to zero.
__global__ void k_final(const float* __restrict__ W2, const float* __restrict__ b2,
                        float* __restrict__ out) {
    __shared__ float v[HID_F];
    int tid = threadIdx.x;
    if (tid < HID_F) v[tid] = g_vacc[tid];
    __syncthreads();
    if (tid < HID_F) g_vacc[tid] = 0.0f;   // restore zero-invariant for next replay
    if (tid < OUT_F) {
        float s = 0.0f;
#pragma unroll 8
        for (int k = 0; k < HID_F; k++) s = fmaf(v[k], W2[k * OUT_F + tid], s);
        out[tid] = s * (1.0f / (float)NN) + b2[tid];
    }
}

// Restore zero-invariant for outdeg/indeg/w (runs on s2, overlapped with k_final).
__global__ void k_tail_zero() {
    int i = blockIdx.x * blockDim.x + threadIdx.x;
    int stride = gridDim.x * blockDim.x;
    for (int t = i; t < NN; t += stride) {
        g_outdeg[t] = 0; g_indeg[t] = 0; g_w[t] = 0.0f;
    }
}

// ---------------- launch ----------------
extern "C" void kernel_launch(void* const* d_in, const int* in_sizes, int n_in,
                              void* d_out, int out_size) {
    const float* feat = (const float*)d_in[0];
    const int*   src  = (const int*)d_in[1];
    const int*   dst  = (const int*)d_in[2];
    const float* W1   = (const float*)d_in[3];
    const float* b1   = (const float*)d_in[4];
    const float* W2   = (const float*)d_in[5];
    const float* b2   = (const float*)d_in[6];
    float* out = (float*)d_out;

    (void)in_sizes; (void)n_in; (void)out_size;

    cudaFuncSetAttribute(k_gemm_mma, cudaFuncAttributeMaxDynamicSharedMemorySize, SM_GEMM_TOTAL);

    // Fork at t=0: branch A (s2) = deg_out -> GEMM ; branch B (default) = deg_in -> CSR.
    // (Latency-bound deg kernels DO overlap; R15 proved merging them regresses.)
    cudaEventRecord(g_ctx.ev_fork, 0);
    cudaStreamWaitEvent(g_ctx.s2, g_ctx.ev_fork, 0);
    k_deg_out<<<1024, 256, 0, g_ctx.s2>>>(src);
    k_gemm_mma<<<(NN + 127) / 128, 256, SM_GEMM_TOTAL, g_ctx.s2>>>(feat, W1);
    cudaEventRecord(g_ctx.ev_join, g_ctx.s2);

    k_deg_in<<<1024, 256>>>(dst);
    k_scan1<<<NB_SCAN, 1024>>>();
    k_scan3<<<NB_SCAN, 1024>>>();
    k_scatter_wsum<<<1024, 256>>>(src, dst);

    // Join before SpMM (needs g_hb + outdeg from s2, CSR/w/c_dst from default).
    cudaStreamWaitEvent(0, g_ctx.ev_join, 0);
    k_spmm_vacc<<<SPMM_GRID, 256>>>(b1);

    // Tail: restore zero-invariant on s2, overlapped with k_final on default.
    cudaEventRecord(g_ctx.ev_spmm, 0);
    cudaStreamWaitEvent(g_ctx.s2, g_ctx.ev_spmm, 0);
    k_tail_zero<<<256, 256, 0, g_ctx.s2>>>();
    cudaEventRecord(g_ctx.ev_tail, g_ctx.s2);

    k_final<<<1, 128>>>(W2, b2, out);
    cudaStreamWaitEvent(0, g_ctx.ev_tail, 0);
}